// round 8
// baseline (speedup 1.0000x reference)
#include <cuda_runtime.h>
#include <cuda_bf16.h>
#include <cstdint>

#define N0_   260000
#define N1_   10240
#define B_    1024
#define E0_   256000
#define E1_   10240
#define IN_C  602
#define HID   256
#define OUT_C 41
#define KHALF 640
#define KTOT  1280
#define NCHUNK 20

// ---------------- scratch ----------------------------------------------------
__device__ float g_a[(size_t)N1_ * KTOT];    // A (tf32-rounded fp32) [10240][1280]
__device__ float g_wt[(size_t)HID * KTOT];   // W^T (tf32-rounded)    [256][1280]
__device__ float g_h[(size_t)N1_ * HID];     // layer-0 output
__device__ float g_w1t[2 * OUT_C * HID];     // [k512][41] = concat(W_l1, W_r1)

// ---------------- portable PTX macros ---------------------------------------
#define CP_ASYNC16(dst, src) \
    asm volatile("cp.async.cg.shared.global [%0], [%1], 16;" \
        :: "r"((uint32_t)(dst)), "l"(src) : "memory")
#define CP_COMMIT() asm volatile("cp.async.commit_group;" ::: "memory")
#define CP_WAIT1()  asm volatile("cp.async.wait_group 1;" ::: "memory")

#define LDMATRIX_X4(r0, r1, r2, r3, addr) \
    asm volatile("ldmatrix.sync.aligned.m8n8.x4.shared.b16 {%0,%1,%2,%3}, [%4];" \
        : "=r"(r0), "=r"(r1), "=r"(r2), "=r"(r3) : "r"((uint32_t)(addr)))

#define MMA_TF32(d, a, b0_, b1_) \
    asm volatile("mma.sync.aligned.m16n8k8.row.col.f32.tf32.tf32.f32 " \
        "{%0,%1,%2,%3}, {%4,%5,%6,%7}, {%8,%9}, {%0,%1,%2,%3};" \
        : "+f"((d)[0]), "+f"((d)[1]), "+f"((d)[2]), "+f"((d)[3]) \
        : "r"((a)[0]), "r"((a)[1]), "r"((a)[2]), "r"((a)[3]), \
          "r"(b0_), "r"(b1_))

#define SWZ128(o) ((o) ^ (((o) >> 3) & 0x70))

// ---------------------------------------------------------------------------
__device__ __forceinline__ int lower_bound_i(const int* __restrict__ a, int n, int v) {
    int lo = 0;
    int hi = n;
    while (lo < hi) {
        int mid = (lo + hi) >> 1;
        if (a[mid] < v) lo = mid + 1; else hi = mid;
    }
    return lo;
}

// round-to-nearest tf32 (unbiased; truncation would bias the K-sum)
__device__ __forceinline__ float tf32r(float v) {
    uint32_t r;
    asm("cvt.rna.tf32.f32 %0, %1;" : "=r"(r) : "f"(v));
    return __uint_as_float(r);
}

// ---------------------------------------------------------------------------
// prep: W_l0/W_r0 -> g_wt (transposed, tf32-rounded); W_l1/W_r1 -> g_w1t
// ---------------------------------------------------------------------------
#define W0_ELEMS (2 * HID * KHALF)
#define W1_ELEMS (2 * OUT_C * HID)

__global__ void prep_w_kernel(const float* __restrict__ Wl0,
                              const float* __restrict__ Wr0,
                              const float* __restrict__ Wl1,
                              const float* __restrict__ Wr1) {
    int i = blockIdx.x * blockDim.x + threadIdx.x;
    if (i < W0_ELEMS) {
        int m = i / (HID * KHALF);
        int rem = i % (HID * KHALF);
        int n = rem / KHALF;
        int k = rem % KHALF;
        const float* W = m ? Wr0 : Wl0;
        float v = (k < IN_C) ? W[(size_t)k * HID + n] : 0.0f;
        g_wt[(size_t)n * KTOT + (size_t)m * KHALF + k] = tf32r(v);
    } else {
        int j = i - W0_ELEMS;
        if (j >= W1_ELEMS) return;
        // g_w1t = [Wl1 flat [HID][OUT_C] ; Wr1 flat [HID][OUT_C]]
        g_w1t[j] = (j < OUT_C * HID) ? Wl1[j] : Wr1[j - OUT_C * HID];
    }
}

// ---------------------------------------------------------------------------
// layer-0 segment mean + x-row copy (tf32-rounded). One CTA per target.
// ---------------------------------------------------------------------------
__global__ __launch_bounds__(256)
void agg0x_kernel(const float* __restrict__ x,
                  const int* __restrict__ src,
                  const int* __restrict__ dst) {
    const int t = blockIdx.x;
    const int start = lower_bound_i(dst, E0_, t);
    const int end   = lower_bound_i(dst, E0_, t + 1);
    const int tid = threadIdx.x;
    const int c0 = 2 * tid;
    const int c1 = 512 + 2 * tid;
    const bool has2 = (tid < 45);

    float2 s0 = make_float2(0.0f, 0.0f);
    float2 s1 = make_float2(0.0f, 0.0f);

    int e = start;
    for (; e + 7 < end; e += 8) {
        const float* p0 = x + (size_t)src[e] * IN_C;
        const float* p1 = x + (size_t)src[e + 1] * IN_C;
        const float* p2 = x + (size_t)src[e + 2] * IN_C;
        const float* p3 = x + (size_t)src[e + 3] * IN_C;
        const float* p4 = x + (size_t)src[e + 4] * IN_C;
        const float* p5 = x + (size_t)src[e + 5] * IN_C;
        const float* p6 = x + (size_t)src[e + 6] * IN_C;
        const float* p7 = x + (size_t)src[e + 7] * IN_C;
        float2 a0 = *(const float2*)(p0 + c0);
        float2 a1 = *(const float2*)(p1 + c0);
        float2 a2 = *(const float2*)(p2 + c0);
        float2 a3 = *(const float2*)(p3 + c0);
        float2 a4 = *(const float2*)(p4 + c0);
        float2 a5 = *(const float2*)(p5 + c0);
        float2 a6 = *(const float2*)(p6 + c0);
        float2 a7 = *(const float2*)(p7 + c0);
        if (has2) {
            float2 b0 = *(const float2*)(p0 + c1);
            float2 b1 = *(const float2*)(p1 + c1);
            float2 b2 = *(const float2*)(p2 + c1);
            float2 b3 = *(const float2*)(p3 + c1);
            float2 b4 = *(const float2*)(p4 + c1);
            float2 b5 = *(const float2*)(p5 + c1);
            float2 b6 = *(const float2*)(p6 + c1);
            float2 b7 = *(const float2*)(p7 + c1);
            s1.x += ((b0.x + b1.x) + (b2.x + b3.x)) + ((b4.x + b5.x) + (b6.x + b7.x));
            s1.y += ((b0.y + b1.y) + (b2.y + b3.y)) + ((b4.y + b5.y) + (b6.y + b7.y));
        }
        s0.x += ((a0.x + a1.x) + (a2.x + a3.x)) + ((a4.x + a5.x) + (a6.x + a7.x));
        s0.y += ((a0.y + a1.y) + (a2.y + a3.y)) + ((a4.y + a5.y) + (a6.y + a7.y));
    }
    for (; e < end; ++e) {
        const float* p0 = x + (size_t)src[e] * IN_C;
        float2 a0 = *(const float2*)(p0 + c0);
        s0.x += a0.x;
        s0.y += a0.y;
        if (has2) {
            float2 b0 = *(const float2*)(p0 + c1);
            s1.x += b0.x;
            s1.y += b0.y;
        }
    }

    const float inv = 1.0f / (float)max(end - start, 1);
    float* A = g_a + (size_t)t * KTOT;
    A[c0] = tf32r(s0.x * inv);
    A[c0 + 1] = tf32r(s0.y * inv);
    if (has2) {
        A[c1] = tf32r(s1.x * inv);
        A[c1 + 1] = tf32r(s1.y * inv);
    } else if (tid < 64) {
        A[c1] = 0.0f;
        A[c1 + 1] = 0.0f;
    }

    // x row t -> cols 640..1279 (tf32-rounded, padded)
    const float* xr = x + (size_t)t * IN_C;
    float2 v0 = *(const float2*)(xr + c0);
    A[KHALF + c0] = tf32r(v0.x);
    A[KHALF + c0 + 1] = tf32r(v0.y);
    if (has2) {
        float2 v1 = *(const float2*)(xr + c1);
        A[KHALF + c1] = tf32r(v1.x);
        A[KHALF + c1 + 1] = tf32r(v1.y);
    } else if (tid < 64) {
        A[KHALF + c1] = 0.0f;
        A[KHALF + c1 + 1] = 0.0f;
    }
}

// ---------------------------------------------------------------------------
// layer-0 GEMM: h = relu(bias + A @ W^T), single-pass tf32 mma.m16n8k8.
// CTA tile 160x128 (grid 64x2 = 128 = one wave), warp tile 80x32, K chunks
// of 64 stored as 2 planes of 32 floats (128B rows -> SW128 conflict-free).
// ---------------------------------------------------------------------------
#define TM        160
#define OFF_A     0u
#define A_PLANE   20480u
#define OFF_B     40960u
#define B_PLANE   16384u
#define STAGE_B   73728u
#define GSM_TOTAL (2 * 73728)

__device__ __forceinline__ void load_stage(uint32_t sb, int kc, int m0, int n0, int tid) {
    #pragma unroll
    for (int j = 0; j < 10; ++j) {
        int i = tid + 256 * j;
        int row = i >> 4;
        int u = i & 15;
        int plane = u >> 3;
        int q = u & 7;
        uint32_t d = sb + OFF_A + (uint32_t)plane * A_PLANE +
                     SWZ128((uint32_t)(row * 128 + q * 16));
        CP_ASYNC16(d, g_a + (size_t)(m0 + row) * KTOT + kc + plane * 32 + q * 4);
    }
    #pragma unroll
    for (int j = 0; j < 8; ++j) {
        int i = tid + 256 * j;
        int row = i >> 4;
        int u = i & 15;
        int plane = u >> 3;
        int q = u & 7;
        uint32_t d = sb + OFF_B + (uint32_t)plane * B_PLANE +
                     SWZ128((uint32_t)(row * 128 + q * 16));
        CP_ASYNC16(d, g_wt + (size_t)(n0 + row) * KTOT + kc + plane * 32 + q * 4);
    }
}

__global__ __launch_bounds__(256, 1)
void gemm0_mma(const float* __restrict__ bias) {
    extern __shared__ char smem_raw[];
    const uint32_t sbase = (uint32_t)__cvta_generic_to_shared(smem_raw);

    const int tid = threadIdx.x;
    const int wid = tid >> 5;
    const int lane = tid & 31;
    const int m0 = (blockIdx.x >> 1) * TM;
    const int n0 = (blockIdx.x & 1) * 128;
    const int wm = (wid & 1) * 80;
    const int wn = (wid >> 1) * 32;

    float acc[5][4][4];
    #pragma unroll
    for (int a = 0; a < 5; ++a)
        #pragma unroll
        for (int b = 0; b < 4; ++b)
            #pragma unroll
            for (int c = 0; c < 4; ++c) acc[a][b][c] = 0.0f;

    const int sub = lane >> 3;
    const int rowsel = (lane & 7) + (sub & 1) * 8;
    const int colsel = (sub >> 1) * 16;

    load_stage(sbase, 0, m0, n0, tid);
    CP_COMMIT();

    for (int c = 0; c < NCHUNK; ++c) {
        if (c + 1 < NCHUNK) {
            load_stage(sbase + (uint32_t)((c + 1) & 1) * STAGE_B, (c + 1) * 64, m0, n0, tid);
        }
        CP_COMMIT();
        CP_WAIT1();
        __syncthreads();

        const uint32_t sA = sbase + (uint32_t)(c & 1) * STAGE_B;
        #pragma unroll
        for (int ks = 0; ks < 8; ++ks) {
            const int plane = ks >> 2;
            const int colb = (ks & 3) * 32 + colsel;

            uint32_t bb[2][4];
            #pragma unroll
            for (int g = 0; g < 2; ++g) {
                uint32_t off = SWZ128((uint32_t)((wn + g * 16 + rowsel) * 128 + colb));
                LDMATRIX_X4(bb[g][0], bb[g][1], bb[g][2], bb[g][3],
                            sA + OFF_B + (uint32_t)plane * B_PLANE + off);
            }

            #pragma unroll
            for (int mf = 0; mf < 5; ++mf) {
                uint32_t a[4];
                uint32_t off = SWZ128((uint32_t)((wm + mf * 16 + rowsel) * 128 + colb));
                LDMATRIX_X4(a[0], a[1], a[2], a[3],
                            sA + OFF_A + (uint32_t)plane * A_PLANE + off);
                #pragma unroll
                for (int g = 0; g < 2; ++g) {
                    MMA_TF32(acc[mf][g * 2 + 0], a, bb[g][0], bb[g][2]);
                    MMA_TF32(acc[mf][g * 2 + 1], a, bb[g][1], bb[g][3]);
                }
            }
        }
        __syncthreads();
    }

    #pragma unroll
    for (int mf = 0; mf < 5; ++mf) {
        #pragma unroll
        for (int nf = 0; nf < 4; ++nf) {
            const int r0 = m0 + wm + mf * 16 + (lane >> 2);
            const int cb = n0 + wn + nf * 8 + (lane & 3) * 2;
            const float b0 = __ldg(bias + cb);
            const float b1 = __ldg(bias + cb + 1);
            float2 v0;
            v0.x = fmaxf(acc[mf][nf][0] + b0, 0.0f);
            v0.y = fmaxf(acc[mf][nf][1] + b1, 0.0f);
            float2 v1;
            v1.x = fmaxf(acc[mf][nf][2] + b0, 0.0f);
            v1.y = fmaxf(acc[mf][nf][3] + b1, 0.0f);
            *(float2*)(g_h + (size_t)r0 * HID + cb) = v0;
            *(float2*)(g_h + (size_t)(r0 + 8) * HID + cb) = v1;
        }
    }
}

// ---------------------------------------------------------------------------
// fused layer-1: warp-per-row; weights cached once per CTA in smem.
// FIX vs rounds 6/7: logits 32..40 are now actually written to d_out.
// ---------------------------------------------------------------------------
#define OUT_SMEM (2 * HID * OUT_C * 4)

__global__ __launch_bounds__(256)
void out_kernel(const int* __restrict__ src, const int* __restrict__ dst,
                const float* __restrict__ b1, float* __restrict__ out) {
    extern __shared__ float sW[];            // [512][41]
    __shared__ float slog[8][OUT_C];

    const int tid = threadIdx.x;
    for (int i = tid; i < 2 * HID * OUT_C; i += 256) {
        sW[i] = g_w1t[i];
    }
    __syncthreads();

    const int w = tid >> 5;
    const int l = tid & 31;
    const int b = blockIdx.x * 8 + w;
    const int start = lower_bound_i(dst, E1_, b);
    const int end   = lower_bound_i(dst, E1_, b + 1);

    float va[8];
    #pragma unroll
    for (int j = 0; j < 8; ++j) va[j] = 0.0f;
    for (int e = start; e < end; ++e) {
        const float* hp = g_h + (size_t)src[e] * HID;
        #pragma unroll
        for (int j = 0; j < 8; ++j) va[j] += hp[l + 32 * j];
    }
    const float inv = 1.0f / (float)max(end - start, 1);
    #pragma unroll
    for (int j = 0; j < 8; ++j) va[j] *= inv;

    float vs[8];
    const float* hb = g_h + (size_t)b * HID;
    #pragma unroll
    for (int j = 0; j < 8; ++j) vs[j] = hb[l + 32 * j];

    #pragma unroll 1
    for (int c = 0; c < OUT_C; ++c) {
        float s = 0.0f;
        #pragma unroll
        for (int j = 0; j < 8; ++j) {
            const int k = l + 32 * j;
            s += va[j] * sW[k * OUT_C + c] + vs[j] * sW[(HID + k) * OUT_C + c];
        }
        #pragma unroll
        for (int o = 16; o; o >>= 1) {
            s += __shfl_xor_sync(0xffffffffu, s, o);
        }
        if (l == 0) slog[w][c] = s + b1[c];
    }
    __syncwarp();

    float v0 = (l < OUT_C) ? slog[w][l] : -3.4e38f;
    float v1 = (l + 32 < OUT_C) ? slog[w][l + 32] : -3.4e38f;
    float m = fmaxf(v0, v1);
    #pragma unroll
    for (int o = 16; o; o >>= 1) {
        m = fmaxf(m, __shfl_xor_sync(0xffffffffu, m, o));
    }
    float es = ((l < OUT_C) ? expf(v0 - m) : 0.0f) +
               ((l + 32 < OUT_C) ? expf(v1 - m) : 0.0f);
    #pragma unroll
    for (int o = 16; o; o >>= 1) {
        es += __shfl_xor_sync(0xffffffffu, es, o);
    }
    const float lse = logf(es);
    if (l < OUT_C) {
        out[(size_t)b * OUT_C + l] = v0 - m - lse;
    }
    if (l + 32 < OUT_C) {
        out[(size_t)b * OUT_C + l + 32] = v1 - m - lse;
    }
}

// ---------------------------------------------------------------------------
extern "C" void kernel_launch(void* const* d_in, const int* in_sizes, int n_in,
                              void* d_out, int out_size) {
    const float* x    = (const float*)d_in[0];
    const float* W_l0 = (const float*)d_in[1];
    const float* b_l0 = (const float*)d_in[2];
    const float* W_r0 = (const float*)d_in[3];
    const float* W_l1 = (const float*)d_in[4];
    const float* b_l1 = (const float*)d_in[5];
    const float* W_r1 = (const float*)d_in[6];
    const int* src0   = (const int*)d_in[7];
    const int* dst0   = (const int*)d_in[8];
    const int* src1   = (const int*)d_in[9];
    const int* dst1   = (const int*)d_in[10];
    float* out = (float*)d_out;

    static int s_attr_done = 0;
    if (!s_attr_done) {
        cudaFuncSetAttribute(gemm0_mma, cudaFuncAttributeMaxDynamicSharedMemorySize,
                             GSM_TOTAL);
        cudaFuncSetAttribute(out_kernel, cudaFuncAttributeMaxDynamicSharedMemorySize,
                             OUT_SMEM);
        s_attr_done = 1;
    }

    prep_w_kernel<<<(W0_ELEMS + W1_ELEMS + 255) / 256, 256>>>(W_l0, W_r0, W_l1, W_r1);
    agg0x_kernel<<<N1_, 256>>>(x, src0, dst0);
    gemm0_mma<<<128, 256, GSM_TOTAL>>>(b_l0);
    out_kernel<<<B_ / 8, 256, OUT_SMEM>>>(src1, dst1, b_l1, out);
}

// round 10
// speedup vs baseline: 1.0806x; 1.0806x over previous
#include <cuda_runtime.h>
#include <cuda_bf16.h>
#include <cstdint>

#define N0_   260000
#define N1_   10240
#define B_    1024
#define E0_   256000
#define E1_   10240
#define IN_C  602
#define HID   256
#define OUT_C 41
#define KHALF 640
#define KTOT  1280
#define NCHUNK 20

// ---------------- scratch ----------------------------------------------------
__device__ float g_a[(size_t)N1_ * KTOT];    // A (tf32-rounded) [10240][1280]
__device__ float g_wt[(size_t)HID * KTOT];   // W^T (tf32-rounded) [256][1280]
__device__ float g_h[(size_t)N1_ * HID];
__device__ float g_w1t[2 * OUT_C * HID];     // [c][k] transposed layer-1 weights

// ---------------- portable PTX macros ---------------------------------------
#define CP_ASYNC16(dst, src) \
    asm volatile("cp.async.cg.shared.global [%0], [%1], 16;" \
        :: "r"((uint32_t)(dst)), "l"(src) : "memory")
#define CP_COMMIT() asm volatile("cp.async.commit_group;" ::: "memory")
#define CP_WAIT1()  asm volatile("cp.async.wait_group 1;" ::: "memory")

#define LDMATRIX_X4(r0, r1, r2, r3, addr) \
    asm volatile("ldmatrix.sync.aligned.m8n8.x4.shared.b16 {%0,%1,%2,%3}, [%4];" \
        : "=r"(r0), "=r"(r1), "=r"(r2), "=r"(r3) : "r"((uint32_t)(addr)))

#define MMA_TF32(d, a, b0_, b1_) \
    asm volatile("mma.sync.aligned.m16n8k8.row.col.f32.tf32.tf32.f32 " \
        "{%0,%1,%2,%3}, {%4,%5,%6,%7}, {%8,%9}, {%0,%1,%2,%3};" \
        : "+f"((d)[0]), "+f"((d)[1]), "+f"((d)[2]), "+f"((d)[3]) \
        : "r"((a)[0]), "r"((a)[1]), "r"((a)[2]), "r"((a)[3]), \
          "r"(b0_), "r"(b1_))

#define SWZ128(o) ((o) ^ (((o) >> 3) & 0x70))

// ---------------------------------------------------------------------------
__device__ __forceinline__ int lower_bound_i(const int* __restrict__ a, int n, int v) {
    int lo = 0;
    int hi = n;
    while (lo < hi) {
        int mid = (lo + hi) >> 1;
        if (a[mid] < v) lo = mid + 1; else hi = mid;
    }
    return lo;
}

__device__ __forceinline__ float tf32r(float v) {
    uint32_t r;
    asm("cvt.rna.tf32.f32 %0, %1;" : "=r"(r) : "f"(v));
    return __uint_as_float(r);
}

// ---------------------------------------------------------------------------
// prep: W_l0/W_r0 -> g_wt (transposed, tf32); W_l1/W_r1 -> g_w1t [c][k]
// ---------------------------------------------------------------------------
#define W0_ELEMS (2 * HID * KHALF)
#define W1_ELEMS (2 * OUT_C * HID)

__global__ void prep_w_kernel(const float* __restrict__ Wl0,
                              const float* __restrict__ Wr0,
                              const float* __restrict__ Wl1,
                              const float* __restrict__ Wr1) {
    int i = blockIdx.x * blockDim.x + threadIdx.x;
    if (i < W0_ELEMS) {
        int m = i / (HID * KHALF);
        int rem = i % (HID * KHALF);
        int n = rem / KHALF;
        int k = rem % KHALF;
        const float* W = m ? Wr0 : Wl0;
        float v = (k < IN_C) ? W[(size_t)k * HID + n] : 0.0f;
        g_wt[(size_t)n * KTOT + (size_t)m * KHALF + k] = tf32r(v);
    } else {
        int j = i - W0_ELEMS;
        if (j >= W1_ELEMS) return;
        int m = j / (OUT_C * HID);
        int rem = j % (OUT_C * HID);
        int c = rem / HID;
        int k = rem % HID;
        const float* W = m ? Wr1 : Wl1;
        g_w1t[j] = W[(size_t)k * OUT_C + c];
    }
}

// ---------------------------------------------------------------------------
// layer-0 segment mean, warp-per-edge gather (float2 loads: x rows are only
// 8B-aligned since IN_C*4 = 2408 B). One CTA (8 warps) per target; lane l
// covers float2 chunks col = 2*(l + 32*i), i<10. Partials reduced via smem.
// ---------------------------------------------------------------------------
__global__ __launch_bounds__(256)
void agg0x_kernel(const float* __restrict__ x,
                  const int* __restrict__ src,
                  const int* __restrict__ dst) {
    __shared__ float sred[8][640];

    const int t = blockIdx.x;
    const int start = lower_bound_i(dst, E0_, t);
    const int end   = lower_bound_i(dst, E0_, t + 1);
    const int tid = threadIdx.x;
    const int w = tid >> 5;
    const int l = tid & 31;

    float2 acc[10];
    #pragma unroll
    for (int i = 0; i < 10; ++i) acc[i] = make_float2(0.f, 0.f);

    for (int e = start + w; e < end; e += 8) {
        const float* p = x + (size_t)src[e] * IN_C;
        #pragma unroll
        for (int i = 0; i < 10; ++i) {
            const int col = 2 * (l + 32 * i);
            if (col + 1 < IN_C) {             // col <= 600 valid (600,601 ok)
                float2 v = *(const float2*)(p + col);
                acc[i].x += v.x;
                acc[i].y += v.y;
            }
        }
    }

    #pragma unroll
    for (int i = 0; i < 10; ++i) {
        const int col = 2 * (l + 32 * i);     // < 640 always
        *(float2*)&sred[w][col] = acc[i];
    }
    __syncthreads();

    const float inv = 1.0f / (float)max(end - start, 1);
    float* A = g_a + (size_t)t * KTOT;

    {
        const int col = tid;                  // 0..255
        float s = sred[0][col] + sred[1][col] + sred[2][col] + sred[3][col]
                + sred[4][col] + sred[5][col] + sred[6][col] + sred[7][col];
        A[col] = tf32r(s * inv);
    }
    {
        const int col = tid + 256;            // 256..511
        float s = sred[0][col] + sred[1][col] + sred[2][col] + sred[3][col]
                + sred[4][col] + sred[5][col] + sred[6][col] + sred[7][col];
        A[col] = tf32r(s * inv);
    }
    if (tid < 128) {
        const int col = tid + 512;            // 512..639 (>=602 are zeros)
        float s = sred[0][col] + sred[1][col] + sred[2][col] + sred[3][col]
                + sred[4][col] + sred[5][col] + sred[6][col] + sred[7][col];
        A[col] = tf32r(s * inv);
    }

    // x row t -> cols 640..1279 (tf32, padded) — proven epilogue (float2, 8B ok)
    const int c0 = 2 * tid;
    const int c1 = 512 + 2 * tid;
    const bool has2 = (tid < 45);
    const float* xr = x + (size_t)t * IN_C;
    float2 v0 = *(const float2*)(xr + c0);
    A[KHALF + c0] = tf32r(v0.x);
    A[KHALF + c0 + 1] = tf32r(v0.y);
    if (has2) {
        float2 v1 = *(const float2*)(xr + c1);
        A[KHALF + c1] = tf32r(v1.x);
        A[KHALF + c1 + 1] = tf32r(v1.y);
    } else if (tid < 64) {
        A[KHALF + c1] = 0.0f;
        A[KHALF + c1 + 1] = 0.0f;
    }
}

// ---------------------------------------------------------------------------
// layer-0 GEMM (proven round-8): tf32 mma.m16n8k8, tile 160x128, grid 128.
// ---------------------------------------------------------------------------
#define TM        160
#define OFF_A     0u
#define A_PLANE   20480u
#define OFF_B     40960u
#define B_PLANE   16384u
#define STAGE_B   73728u
#define GSM_TOTAL (2 * 73728)

__device__ __forceinline__ void load_stage(uint32_t sb, int kc, int m0, int n0, int tid) {
    #pragma unroll
    for (int j = 0; j < 10; ++j) {
        int i = tid + 256 * j;
        int row = i >> 4;
        int u = i & 15;
        int plane = u >> 3;
        int q = u & 7;
        uint32_t d = sb + OFF_A + (uint32_t)plane * A_PLANE +
                     SWZ128((uint32_t)(row * 128 + q * 16));
        CP_ASYNC16(d, g_a + (size_t)(m0 + row) * KTOT + kc + plane * 32 + q * 4);
    }
    #pragma unroll
    for (int j = 0; j < 8; ++j) {
        int i = tid + 256 * j;
        int row = i >> 4;
        int u = i & 15;
        int plane = u >> 3;
        int q = u & 7;
        uint32_t d = sb + OFF_B + (uint32_t)plane * B_PLANE +
                     SWZ128((uint32_t)(row * 128 + q * 16));
        CP_ASYNC16(d, g_wt + (size_t)(n0 + row) * KTOT + kc + plane * 32 + q * 4);
    }
}

__global__ __launch_bounds__(256, 1)
void gemm0_mma(const float* __restrict__ bias) {
    extern __shared__ char smem_raw[];
    const uint32_t sbase = (uint32_t)__cvta_generic_to_shared(smem_raw);

    const int tid = threadIdx.x;
    const int wid = tid >> 5;
    const int lane = tid & 31;
    const int m0 = (blockIdx.x >> 1) * TM;
    const int n0 = (blockIdx.x & 1) * 128;
    const int wm = (wid & 1) * 80;
    const int wn = (wid >> 1) * 32;

    float acc[5][4][4];
    #pragma unroll
    for (int a = 0; a < 5; ++a)
        #pragma unroll
        for (int b = 0; b < 4; ++b)
            #pragma unroll
            for (int c = 0; c < 4; ++c) acc[a][b][c] = 0.0f;

    const int sub = lane >> 3;
    const int rowsel = (lane & 7) + (sub & 1) * 8;
    const int colsel = (sub >> 1) * 16;

    load_stage(sbase, 0, m0, n0, tid);
    CP_COMMIT();

    for (int c = 0; c < NCHUNK; ++c) {
        if (c + 1 < NCHUNK) {
            load_stage(sbase + (uint32_t)((c + 1) & 1) * STAGE_B, (c + 1) * 64, m0, n0, tid);
        }
        CP_COMMIT();
        CP_WAIT1();
        __syncthreads();

        const uint32_t sA = sbase + (uint32_t)(c & 1) * STAGE_B;
        #pragma unroll
        for (int ks = 0; ks < 8; ++ks) {
            const int plane = ks >> 2;
            const int colb = (ks & 3) * 32 + colsel;

            uint32_t bb[2][4];
            #pragma unroll
            for (int g = 0; g < 2; ++g) {
                uint32_t off = SWZ128((uint32_t)((wn + g * 16 + rowsel) * 128 + colb));
                LDMATRIX_X4(bb[g][0], bb[g][1], bb[g][2], bb[g][3],
                            sA + OFF_B + (uint32_t)plane * B_PLANE + off);
            }

            #pragma unroll
            for (int mf = 0; mf < 5; ++mf) {
                uint32_t a[4];
                uint32_t off = SWZ128((uint32_t)((wm + mf * 16 + rowsel) * 128 + colb));
                LDMATRIX_X4(a[0], a[1], a[2], a[3],
                            sA + OFF_A + (uint32_t)plane * A_PLANE + off);
                #pragma unroll
                for (int g = 0; g < 2; ++g) {
                    MMA_TF32(acc[mf][g * 2 + 0], a, bb[g][0], bb[g][2]);
                    MMA_TF32(acc[mf][g * 2 + 1], a, bb[g][1], bb[g][3]);
                }
            }
        }
        __syncthreads();
    }

    #pragma unroll
    for (int mf = 0; mf < 5; ++mf) {
        #pragma unroll
        for (int nf = 0; nf < 4; ++nf) {
            const int r0 = m0 + wm + mf * 16 + (lane >> 2);
            const int cb = n0 + wn + nf * 8 + (lane & 3) * 2;
            const float b0 = __ldg(bias + cb);
            const float b1 = __ldg(bias + cb + 1);
            float2 v0;
            v0.x = fmaxf(acc[mf][nf][0] + b0, 0.0f);
            v0.y = fmaxf(acc[mf][nf][1] + b1, 0.0f);
            float2 v1;
            v1.x = fmaxf(acc[mf][nf][2] + b0, 0.0f);
            v1.y = fmaxf(acc[mf][nf][3] + b1, 0.0f);
            *(float2*)(g_h + (size_t)r0 * HID + cb) = v0;
            *(float2*)(g_h + (size_t)(r0 + 8) * HID + cb) = v1;
        }
    }
}

// ---------------------------------------------------------------------------
// fused layer-1 (proven round-5 version): one CTA (256 thr) per batch row.
// ---------------------------------------------------------------------------
__global__ __launch_bounds__(256)
void out_kernel(const int* __restrict__ src, const int* __restrict__ dst,
                const float* __restrict__ b1, float* __restrict__ out) {
    __shared__ float sA[HID];
    __shared__ float sH[HID];
    __shared__ float logits[OUT_C];

    const int b = blockIdx.x;
    const int tid = threadIdx.x;
    const int start = lower_bound_i(dst, E1_, b);
    const int end   = lower_bound_i(dst, E1_, b + 1);

    float acc = 0.0f;
    for (int e = start; e < end; ++e) {
        acc += g_h[(size_t)src[e] * HID + tid];
    }
    sA[tid] = acc / (float)max(end - start, 1);
    sH[tid] = g_h[(size_t)b * HID + tid];
    __syncthreads();

    const int w = tid >> 5;
    const int l = tid & 31;
    for (int c = w; c < OUT_C; c += 8) {
        const float* wl = g_w1t + (size_t)c * HID;
        const float* wr = g_w1t + (size_t)(OUT_C + c) * HID;
        float s = 0.0f;
        #pragma unroll
        for (int k = l; k < HID; k += 32) {
            s += sA[k] * wl[k] + sH[k] * wr[k];
        }
        #pragma unroll
        for (int o = 16; o; o >>= 1) {
            s += __shfl_xor_sync(0xffffffffu, s, o);
        }
        if (l == 0) logits[c] = s + b1[c];
    }
    __syncthreads();

    if (tid < 32) {
        float v0 = (tid < OUT_C) ? logits[tid] : -3.4e38f;
        float v1 = (tid + 32 < OUT_C) ? logits[tid + 32] : -3.4e38f;
        float m = fmaxf(v0, v1);
        #pragma unroll
        for (int o = 16; o; o >>= 1) {
            m = fmaxf(m, __shfl_xor_sync(0xffffffffu, m, o));
        }
        float es = ((tid < OUT_C) ? expf(v0 - m) : 0.0f) +
                   ((tid + 32 < OUT_C) ? expf(v1 - m) : 0.0f);
        #pragma unroll
        for (int o = 16; o; o >>= 1) {
            es += __shfl_xor_sync(0xffffffffu, es, o);
        }
        float lse = logf(es);
        if (tid < OUT_C) out[(size_t)b * OUT_C + tid] = v0 - m - lse;
        if (tid + 32 < OUT_C) out[(size_t)b * OUT_C + tid + 32] = v1 - m - lse;
    }
}

// ---------------------------------------------------------------------------
extern "C" void kernel_launch(void* const* d_in, const int* in_sizes, int n_in,
                              void* d_out, int out_size) {
    const float* x    = (const float*)d_in[0];
    const float* W_l0 = (const float*)d_in[1];
    const float* b_l0 = (const float*)d_in[2];
    const float* W_r0 = (const float*)d_in[3];
    const float* W_l1 = (const float*)d_in[4];
    const float* b_l1 = (const float*)d_in[5];
    const float* W_r1 = (const float*)d_in[6];
    const int* src0   = (const int*)d_in[7];
    const int* dst0   = (const int*)d_in[8];
    const int* src1   = (const int*)d_in[9];
    const int* dst1   = (const int*)d_in[10];
    float* out = (float*)d_out;

    static int s_attr_done = 0;
    if (!s_attr_done) {
        cudaFuncSetAttribute(gemm0_mma, cudaFuncAttributeMaxDynamicSharedMemorySize,
                             GSM_TOTAL);
        s_attr_done = 1;
    }

    prep_w_kernel<<<(W0_ELEMS + W1_ELEMS + 255) / 256, 256>>>(W_l0, W_r0, W_l1, W_r1);
    agg0x_kernel<<<N1_, 256>>>(x, src0, dst0);
    gemm0_mma<<<128, 256, GSM_TOTAL>>>(b_l0);
    out_kernel<<<B_, 256>>>(src1, dst1, b_l1, out);
}

// round 11
// speedup vs baseline: 1.2284x; 1.1368x over previous
#include <cuda_runtime.h>
#include <cuda_fp16.h>
#include <cstdint>

#define N0_   260000
#define N1_   10240
#define B_    1024
#define E0_   256000
#define E1_   10240
#define IN_C  602
#define HID   256
#define OUT_C 41
#define KHALF 640
#define KTOT  1280
#define NCHUNK 20

// ---------------- scratch ----------------------------------------------------
__device__ __half g_a[(size_t)N1_ * KTOT];    // A (fp16) [10240][1280]
__device__ __half g_wt[(size_t)HID * KTOT];   // W^T (fp16) [256][1280]
__device__ float g_h[(size_t)N1_ * HID];
__device__ float g_w1t[2 * OUT_C * HID];      // [c][k] transposed layer-1 weights

// ---------------- portable PTX macros ---------------------------------------
#define CP_ASYNC16(dst, src) \
    asm volatile("cp.async.cg.shared.global [%0], [%1], 16;" \
        :: "r"((uint32_t)(dst)), "l"(src) : "memory")
#define CP_COMMIT() asm volatile("cp.async.commit_group;" ::: "memory")
#define CP_WAIT1()  asm volatile("cp.async.wait_group 1;" ::: "memory")

#define LDMATRIX_X4(r0, r1, r2, r3, addr) \
    asm volatile("ldmatrix.sync.aligned.m8n8.x4.shared.b16 {%0,%1,%2,%3}, [%4];" \
        : "=r"(r0), "=r"(r1), "=r"(r2), "=r"(r3) : "r"((uint32_t)(addr)))

#define MMA_FP16(d, a, b0_, b1_) \
    asm volatile("mma.sync.aligned.m16n8k16.row.col.f32.f16.f16.f32 " \
        "{%0,%1,%2,%3}, {%4,%5,%6,%7}, {%8,%9}, {%0,%1,%2,%3};" \
        : "+f"((d)[0]), "+f"((d)[1]), "+f"((d)[2]), "+f"((d)[3]) \
        : "r"((a)[0]), "r"((a)[1]), "r"((a)[2]), "r"((a)[3]), \
          "r"(b0_), "r"(b1_))

#define SWZ128(o) ((o) ^ (((o) >> 3) & 0x70))

// ---------------------------------------------------------------------------
__device__ __forceinline__ int lower_bound_i(const int* __restrict__ a, int n, int v) {
    int lo = 0;
    int hi = n;
    while (lo < hi) {
        int mid = (lo + hi) >> 1;
        if (a[mid] < v) lo = mid + 1; else hi = mid;
    }
    return lo;
}

// ---------------------------------------------------------------------------
// fused: layer-0 segment mean (+x-row copy) AND weight prep, one launch.
// blocks [0, N1)         : agg for target t (+ x row t), fp16 outputs
// blocks [N1, N1+1362)   : weight conversion (W0 -> g_wt fp16, W1 -> g_w1t)
// ---------------------------------------------------------------------------
#define W0_ELEMS (2 * HID * KHALF)
#define W1_ELEMS (2 * OUT_C * HID)
#define PREP_BLOCKS ((W0_ELEMS + W1_ELEMS + 255) / 256)

__global__ __launch_bounds__(256)
void agg0x_kernel(const float* __restrict__ x,
                  const int* __restrict__ src,
                  const int* __restrict__ dst,
                  const float* __restrict__ Wl0,
                  const float* __restrict__ Wr0,
                  const float* __restrict__ Wl1,
                  const float* __restrict__ Wr1) {
    __shared__ float sred[8][640];

    const int t = blockIdx.x;
    const int tid = threadIdx.x;

    if (t >= N1_) {
        // ---- weight prep blocks ----
        int i = (t - N1_) * 256 + tid;
        if (i < W0_ELEMS) {
            int m = i / (HID * KHALF);
            int rem = i % (HID * KHALF);
            int n = rem / KHALF;
            int k = rem % KHALF;
            const float* W = m ? Wr0 : Wl0;
            float v = (k < IN_C) ? W[(size_t)k * HID + n] : 0.0f;
            g_wt[(size_t)n * KTOT + (size_t)m * KHALF + k] = __float2half_rn(v);
        } else {
            int j = i - W0_ELEMS;
            if (j < W1_ELEMS) {
                int m = j / (OUT_C * HID);
                int rem = j % (OUT_C * HID);
                int c = rem / HID;
                int k = rem % HID;
                const float* W = m ? Wr1 : Wl1;
                g_w1t[j] = W[(size_t)k * OUT_C + c];
            }
        }
        return;
    }

    // ---- aggregation block for target t ----
    const int start = lower_bound_i(dst, E0_, t);
    const int end   = lower_bound_i(dst, E0_, t + 1);
    const int w = tid >> 5;
    const int l = tid & 31;

    float2 acc[10];
    #pragma unroll
    for (int i = 0; i < 10; ++i) acc[i] = make_float2(0.f, 0.f);

    for (int e = start + w; e < end; e += 8) {
        const float* p = x + (size_t)src[e] * IN_C;
        #pragma unroll
        for (int i = 0; i < 10; ++i) {
            const int col = 2 * (l + 32 * i);
            if (col + 1 < IN_C) {
                float2 v = *(const float2*)(p + col);
                acc[i].x += v.x;
                acc[i].y += v.y;
            }
        }
    }

    #pragma unroll
    for (int i = 0; i < 10; ++i) {
        const int col = 2 * (l + 32 * i);
        *(float2*)&sred[w][col] = acc[i];
    }
    __syncthreads();

    const float inv = 1.0f / (float)max(end - start, 1);
    __half* A = g_a + (size_t)t * KTOT;

    {
        const int col = tid;
        float s = sred[0][col] + sred[1][col] + sred[2][col] + sred[3][col]
                + sred[4][col] + sred[5][col] + sred[6][col] + sred[7][col];
        A[col] = __float2half_rn(s * inv);
    }
    {
        const int col = tid + 256;
        float s = sred[0][col] + sred[1][col] + sred[2][col] + sred[3][col]
                + sred[4][col] + sred[5][col] + sred[6][col] + sred[7][col];
        A[col] = __float2half_rn(s * inv);
    }
    if (tid < 128) {
        const int col = tid + 512;
        float s = sred[0][col] + sred[1][col] + sred[2][col] + sred[3][col]
                + sred[4][col] + sred[5][col] + sred[6][col] + sred[7][col];
        A[col] = __float2half_rn(s * inv);
    }

    // x row t -> cols 640..1279 (fp16, padded)
    const int c0 = 2 * tid;
    const int c1 = 512 + 2 * tid;
    const bool has2 = (tid < 45);
    const float* xr = x + (size_t)t * IN_C;
    float2 v0 = *(const float2*)(xr + c0);
    A[KHALF + c0] = __float2half_rn(v0.x);
    A[KHALF + c0 + 1] = __float2half_rn(v0.y);
    if (has2) {
        float2 v1 = *(const float2*)(xr + c1);
        A[KHALF + c1] = __float2half_rn(v1.x);
        A[KHALF + c1 + 1] = __float2half_rn(v1.y);
    } else if (tid < 64) {
        A[KHALF + c1] = __float2half_rn(0.0f);
        A[KHALF + c1 + 1] = __float2half_rn(0.0f);
    }
}

// ---------------------------------------------------------------------------
// layer-0 GEMM: single-pass fp16 mma.m16n8k16 (same 10-bit mantissa as tf32).
// Proven round-5 structure: tile 160x128, grid 128 = one wave, warp 80x32,
// cp.async 2-stage, SW128 smem (64-half rows = 128B), ldmatrix.
// ---------------------------------------------------------------------------
#define TM        160
#define OFF_A     0u
#define OFF_B     20480u
#define STAGE_B   36864u
#define GSM_TOTAL (2 * 36864)

__device__ __forceinline__ void load_stage(uint32_t sb, int kc, int m0, int n0, int tid) {
    #pragma unroll
    for (int j = 0; j < 5; ++j) {
        int i = tid + 256 * j;
        int row = i >> 3;
        int q = i & 7;
        uint32_t d = sb + OFF_A + SWZ128((uint32_t)(row * 128 + q * 16));
        CP_ASYNC16(d, g_a + (size_t)(m0 + row) * KTOT + kc + q * 8);
    }
    #pragma unroll
    for (int j = 0; j < 4; ++j) {
        int i = tid + 256 * j;
        int row = i >> 3;
        int q = i & 7;
        uint32_t d = sb + OFF_B + SWZ128((uint32_t)(row * 128 + q * 16));
        CP_ASYNC16(d, g_wt + (size_t)(n0 + row) * KTOT + kc + q * 8);
    }
}

__global__ __launch_bounds__(256, 1)
void gemm0_mma(const float* __restrict__ bias) {
    extern __shared__ char smem_raw[];
    const uint32_t sbase = (uint32_t)__cvta_generic_to_shared(smem_raw);

    const int tid = threadIdx.x;
    const int wid = tid >> 5;
    const int lane = tid & 31;
    const int m0 = (blockIdx.x >> 1) * TM;
    const int n0 = (blockIdx.x & 1) * 128;
    const int wm = (wid & 1) * 80;
    const int wn = (wid >> 1) * 32;

    float acc[5][4][4];
    #pragma unroll
    for (int a = 0; a < 5; ++a)
        #pragma unroll
        for (int b = 0; b < 4; ++b)
            #pragma unroll
            for (int c = 0; c < 4; ++c) acc[a][b][c] = 0.0f;

    const int lrow = lane & 15;
    const int lcol16 = (lane >> 4) * 16;

    load_stage(sbase, 0, m0, n0, tid);
    CP_COMMIT();

    for (int c = 0; c < NCHUNK; ++c) {
        if (c + 1 < NCHUNK) {
            load_stage(sbase + (uint32_t)((c + 1) & 1) * STAGE_B, (c + 1) * 64, m0, n0, tid);
        }
        CP_COMMIT();
        CP_WAIT1();
        __syncthreads();

        const uint32_t sA = sbase + (uint32_t)(c & 1) * STAGE_B;
        #pragma unroll
        for (int ks = 0; ks < 4; ++ks) {
            const int colb = ks * 32 + lcol16;

            uint32_t bh[2][4];
            #pragma unroll
            for (int g = 0; g < 2; ++g) {
                uint32_t off = SWZ128((uint32_t)((wn + g * 16 + lrow) * 128 + colb));
                LDMATRIX_X4(bh[g][0], bh[g][1], bh[g][2], bh[g][3], sA + OFF_B + off);
            }

            #pragma unroll
            for (int mf = 0; mf < 5; ++mf) {
                uint32_t ah[4];
                uint32_t off = SWZ128((uint32_t)((wm + mf * 16 + lrow) * 128 + colb));
                LDMATRIX_X4(ah[0], ah[1], ah[2], ah[3], sA + OFF_A + off);
                #pragma unroll
                for (int g = 0; g < 2; ++g) {
                    MMA_FP16(acc[mf][g * 2 + 0], ah, bh[g][0], bh[g][2]);
                    MMA_FP16(acc[mf][g * 2 + 1], ah, bh[g][1], bh[g][3]);
                }
            }
        }
        __syncthreads();
    }

    #pragma unroll
    for (int mf = 0; mf < 5; ++mf) {
        #pragma unroll
        for (int nf = 0; nf < 4; ++nf) {
            const int r0 = m0 + wm + mf * 16 + (lane >> 2);
            const int cb = n0 + wn + nf * 8 + (lane & 3) * 2;
            const float b0 = __ldg(bias + cb);
            const float b1 = __ldg(bias + cb + 1);
            float2 v0;
            v0.x = fmaxf(acc[mf][nf][0] + b0, 0.0f);
            v0.y = fmaxf(acc[mf][nf][1] + b1, 0.0f);
            float2 v1;
            v1.x = fmaxf(acc[mf][nf][2] + b0, 0.0f);
            v1.y = fmaxf(acc[mf][nf][3] + b1, 0.0f);
            *(float2*)(g_h + (size_t)r0 * HID + cb) = v0;
            *(float2*)(g_h + (size_t)(r0 + 8) * HID + cb) = v1;
        }
    }
}

// ---------------------------------------------------------------------------
// fused layer-1 (proven round-5 version): one CTA (256 thr) per batch row.
// ---------------------------------------------------------------------------
__global__ __launch_bounds__(256)
void out_kernel(const int* __restrict__ src, const int* __restrict__ dst,
                const float* __restrict__ b1, float* __restrict__ out) {
    __shared__ float sA[HID];
    __shared__ float sH[HID];
    __shared__ float logits[OUT_C];

    const int b = blockIdx.x;
    const int tid = threadIdx.x;
    const int start = lower_bound_i(dst, E1_, b);
    const int end   = lower_bound_i(dst, E1_, b + 1);

    float acc = 0.0f;
    for (int e = start; e < end; ++e) {
        acc += g_h[(size_t)src[e] * HID + tid];
    }
    sA[tid] = acc / (float)max(end - start, 1);
    sH[tid] = g_h[(size_t)b * HID + tid];
    __syncthreads();

    const int w = tid >> 5;
    const int l = tid & 31;
    for (int c = w; c < OUT_C; c += 8) {
        const float* wl = g_w1t + (size_t)c * HID;
        const float* wr = g_w1t + (size_t)(OUT_C + c) * HID;
        float s = 0.0f;
        #pragma unroll
        for (int k = l; k < HID; k += 32) {
            s += sA[k] * wl[k] + sH[k] * wr[k];
        }
        #pragma unroll
        for (int o = 16; o; o >>= 1) {
            s += __shfl_xor_sync(0xffffffffu, s, o);
        }
        if (l == 0) logits[c] = s + b1[c];
    }
    __syncthreads();

    if (tid < 32) {
        float v0 = (tid < OUT_C) ? logits[tid] : -3.4e38f;
        float v1 = (tid + 32 < OUT_C) ? logits[tid + 32] : -3.4e38f;
        float m = fmaxf(v0, v1);
        #pragma unroll
        for (int o = 16; o; o >>= 1) {
            m = fmaxf(m, __shfl_xor_sync(0xffffffffu, m, o));
        }
        float es = ((tid < OUT_C) ? expf(v0 - m) : 0.0f) +
                   ((tid + 32 < OUT_C) ? expf(v1 - m) : 0.0f);
        #pragma unroll
        for (int o = 16; o; o >>= 1) {
            es += __shfl_xor_sync(0xffffffffu, es, o);
        }
        float lse = logf(es);
        if (tid < OUT_C) out[(size_t)b * OUT_C + tid] = v0 - m - lse;
        if (tid + 32 < OUT_C) out[(size_t)b * OUT_C + tid + 32] = v1 - m - lse;
    }
}

// ---------------------------------------------------------------------------
extern "C" void kernel_launch(void* const* d_in, const int* in_sizes, int n_in,
                              void* d_out, int out_size) {
    const float* x    = (const float*)d_in[0];
    const float* W_l0 = (const float*)d_in[1];
    const float* b_l0 = (const float*)d_in[2];
    const float* W_r0 = (const float*)d_in[3];
    const float* W_l1 = (const float*)d_in[4];
    const float* b_l1 = (const float*)d_in[5];
    const float* W_r1 = (const float*)d_in[6];
    const int* src0   = (const int*)d_in[7];
    const int* dst0   = (const int*)d_in[8];
    const int* src1   = (const int*)d_in[9];
    const int* dst1   = (const int*)d_in[10];
    float* out = (float*)d_out;

    static int s_attr_done = 0;
    if (!s_attr_done) {
        cudaFuncSetAttribute(gemm0_mma, cudaFuncAttributeMaxDynamicSharedMemorySize,
                             GSM_TOTAL);
        s_attr_done = 1;
    }

    agg0x_kernel<<<N1_ + PREP_BLOCKS, 256>>>(x, src0, dst0, W_l0, W_r0, W_l1, W_r1);
    gemm0_mma<<<128, 256, GSM_TOTAL>>>(b_l0);
    out_kernel<<<B_, 256>>>(src1, dst1, b_l1, out);
}

// round 12
// speedup vs baseline: 1.4746x; 1.2004x over previous
#include <cuda_runtime.h>
#include <cuda_fp16.h>
#include <cstdint>

#define N0_   260000
#define N1_   10240
#define B_    1024
#define E0_   256000
#define E1_   10240
#define IN_C  602
#define HID   256
#define OUT_C 41
#define KHALF 640
#define KTOT  1280
#define NCHUNK 20

// ---------------- scratch ----------------------------------------------------
__device__ __half g_a[(size_t)N1_ * KTOT];    // A (fp16) [10240][1280]
__device__ __half g_wt[(size_t)HID * KTOT];   // W^T (fp16) [256][1280]
__device__ float g_h[(size_t)N1_ * HID];
__device__ float g_w1t[2 * OUT_C * HID];      // [c][k] transposed layer-1 weights
__device__ int   g_rp0[N1_ + 1];              // CSR row ptr, layer 0
__device__ int   g_rp1[B_ + 1];               // CSR row ptr, layer 1

// ---------------- portable PTX macros ---------------------------------------
#define CP_ASYNC16(dst, src) \
    asm volatile("cp.async.cg.shared.global [%0], [%1], 16;" \
        :: "r"((uint32_t)(dst)), "l"(src) : "memory")
#define CP_COMMIT() asm volatile("cp.async.commit_group;" ::: "memory")
#define CP_WAIT1()  asm volatile("cp.async.wait_group 1;" ::: "memory")

#define LDMATRIX_X4(r0, r1, r2, r3, addr) \
    asm volatile("ldmatrix.sync.aligned.m8n8.x4.shared.b16 {%0,%1,%2,%3}, [%4];" \
        : "=r"(r0), "=r"(r1), "=r"(r2), "=r"(r3) : "r"((uint32_t)(addr)))

#define MMA_FP16(d, a, b0_, b1_) \
    asm volatile("mma.sync.aligned.m16n8k16.row.col.f32.f16.f16.f32 " \
        "{%0,%1,%2,%3}, {%4,%5,%6,%7}, {%8,%9}, {%0,%1,%2,%3};" \
        : "+f"((d)[0]), "+f"((d)[1]), "+f"((d)[2]), "+f"((d)[3]) \
        : "r"((a)[0]), "r"((a)[1]), "r"((a)[2]), "r"((a)[3]), \
          "r"(b0_), "r"(b1_))

#define SWZ128(o) ((o) ^ (((o) >> 3) & 0x70))

// ---------------------------------------------------------------------------
__device__ __forceinline__ int lower_bound_i(const int* __restrict__ a, int n, int v) {
    int lo = 0;
    int hi = n;
    while (lo < hi) {
        int mid = (lo + hi) >> 1;
        if (a[mid] < v) lo = mid + 1; else hi = mid;
    }
    return lo;
}

// ---------------------------------------------------------------------------
// rowptr: parallel binary searches (one thread per target), both layers.
// ---------------------------------------------------------------------------
__global__ void rowptr_kernel(const int* __restrict__ dst0,
                              const int* __restrict__ dst1) {
    int i = blockIdx.x * blockDim.x + threadIdx.x;
    if (i <= N1_) g_rp0[i] = lower_bound_i(dst0, E0_, i);
    if (i <= B_)  g_rp1[i] = lower_bound_i(dst1, E1_, i);
}

// ---------------------------------------------------------------------------
// fused: layer-0 segment mean (+x-row copy) AND weight prep, one launch.
// blocks [0, N1)       : agg for target t (+ x row t), fp16 outputs
// blocks [N1, ...)     : weight conversion
// ---------------------------------------------------------------------------
#define W0_ELEMS (2 * HID * KHALF)
#define W1_ELEMS (2 * OUT_C * HID)
#define PREP_BLOCKS ((W0_ELEMS + W1_ELEMS + 255) / 256)

__global__ __launch_bounds__(256)
void agg0x_kernel(const float* __restrict__ x,
                  const int* __restrict__ src,
                  const float* __restrict__ Wl0,
                  const float* __restrict__ Wr0,
                  const float* __restrict__ Wl1,
                  const float* __restrict__ Wr1) {
    __shared__ float sred[8][640];

    const int t = blockIdx.x;
    const int tid = threadIdx.x;

    if (t >= N1_) {
        int i = (t - N1_) * 256 + tid;
        if (i < W0_ELEMS) {
            int m = i / (HID * KHALF);
            int rem = i % (HID * KHALF);
            int n = rem / KHALF;
            int k = rem % KHALF;
            const float* W = m ? Wr0 : Wl0;
            float v = (k < IN_C) ? W[(size_t)k * HID + n] : 0.0f;
            g_wt[(size_t)n * KTOT + (size_t)m * KHALF + k] = __float2half_rn(v);
        } else {
            int j = i - W0_ELEMS;
            if (j < W1_ELEMS) {
                int m = j / (OUT_C * HID);
                int rem = j % (OUT_C * HID);
                int c = rem / HID;
                int k = rem % HID;
                const float* W = m ? Wr1 : Wl1;
                g_w1t[j] = W[(size_t)k * OUT_C + c];
            }
        }
        return;
    }

    const int start = g_rp0[t];
    const int end   = g_rp0[t + 1];
    const int w = tid >> 5;
    const int l = tid & 31;

    float2 acc[10];
    #pragma unroll
    for (int i = 0; i < 10; ++i) acc[i] = make_float2(0.f, 0.f);

    for (int e = start + w; e < end; e += 8) {
        const float* p = x + (size_t)src[e] * IN_C;
        #pragma unroll
        for (int i = 0; i < 10; ++i) {
            const int col = 2 * (l + 32 * i);
            if (col + 1 < IN_C) {
                float2 v = *(const float2*)(p + col);
                acc[i].x += v.x;
                acc[i].y += v.y;
            }
        }
    }

    #pragma unroll
    for (int i = 0; i < 10; ++i) {
        const int col = 2 * (l + 32 * i);
        *(float2*)&sred[w][col] = acc[i];
    }
    __syncthreads();

    const float inv = 1.0f / (float)max(end - start, 1);
    __half* A = g_a + (size_t)t * KTOT;

    {
        const int col = tid;
        float s = sred[0][col] + sred[1][col] + sred[2][col] + sred[3][col]
                + sred[4][col] + sred[5][col] + sred[6][col] + sred[7][col];
        A[col] = __float2half_rn(s * inv);
    }
    {
        const int col = tid + 256;
        float s = sred[0][col] + sred[1][col] + sred[2][col] + sred[3][col]
                + sred[4][col] + sred[5][col] + sred[6][col] + sred[7][col];
        A[col] = __float2half_rn(s * inv);
    }
    if (tid < 128) {
        const int col = tid + 512;
        float s = sred[0][col] + sred[1][col] + sred[2][col] + sred[3][col]
                + sred[4][col] + sred[5][col] + sred[6][col] + sred[7][col];
        A[col] = __float2half_rn(s * inv);
    }

    // x row t -> cols 640..1279 (fp16, padded)
    const int c0 = 2 * tid;
    const int c1 = 512 + 2 * tid;
    const bool has2 = (tid < 45);
    const float* xr = x + (size_t)t * IN_C;
    float2 v0 = *(const float2*)(xr + c0);
    A[KHALF + c0] = __float2half_rn(v0.x);
    A[KHALF + c0 + 1] = __float2half_rn(v0.y);
    if (has2) {
        float2 v1 = *(const float2*)(xr + c1);
        A[KHALF + c1] = __float2half_rn(v1.x);
        A[KHALF + c1 + 1] = __float2half_rn(v1.y);
    } else if (tid < 64) {
        A[KHALF + c1] = __float2half_rn(0.0f);
        A[KHALF + c1 + 1] = __float2half_rn(0.0f);
    }
}

// ---------------------------------------------------------------------------
// layer-0 GEMM (proven round-11): fp16 mma.m16n8k16, tile 160x128, grid 128.
// ---------------------------------------------------------------------------
#define TM        160
#define OFF_A     0u
#define OFF_B     20480u
#define STAGE_B   36864u
#define GSM_TOTAL (2 * 36864)

__device__ __forceinline__ void load_stage(uint32_t sb, int kc, int m0, int n0, int tid) {
    #pragma unroll
    for (int j = 0; j < 5; ++j) {
        int i = tid + 256 * j;
        int row = i >> 3;
        int q = i & 7;
        uint32_t d = sb + OFF_A + SWZ128((uint32_t)(row * 128 + q * 16));
        CP_ASYNC16(d, g_a + (size_t)(m0 + row) * KTOT + kc + q * 8);
    }
    #pragma unroll
    for (int j = 0; j < 4; ++j) {
        int i = tid + 256 * j;
        int row = i >> 3;
        int q = i & 7;
        uint32_t d = sb + OFF_B + SWZ128((uint32_t)(row * 128 + q * 16));
        CP_ASYNC16(d, g_wt + (size_t)(n0 + row) * KTOT + kc + q * 8);
    }
}

__global__ __launch_bounds__(256, 1)
void gemm0_mma(const float* __restrict__ bias) {
    extern __shared__ char smem_raw[];
    const uint32_t sbase = (uint32_t)__cvta_generic_to_shared(smem_raw);

    const int tid = threadIdx.x;
    const int wid = tid >> 5;
    const int lane = tid & 31;
    const int m0 = (blockIdx.x >> 1) * TM;
    const int n0 = (blockIdx.x & 1) * 128;
    const int wm = (wid & 1) * 80;
    const int wn = (wid >> 1) * 32;

    float acc[5][4][4];
    #pragma unroll
    for (int a = 0; a < 5; ++a)
        #pragma unroll
        for (int b = 0; b < 4; ++b)
            #pragma unroll
            for (int c = 0; c < 4; ++c) acc[a][b][c] = 0.0f;

    const int lrow = lane & 15;
    const int lcol16 = (lane >> 4) * 16;

    load_stage(sbase, 0, m0, n0, tid);
    CP_COMMIT();

    for (int c = 0; c < NCHUNK; ++c) {
        if (c + 1 < NCHUNK) {
            load_stage(sbase + (uint32_t)((c + 1) & 1) * STAGE_B, (c + 1) * 64, m0, n0, tid);
        }
        CP_COMMIT();
        CP_WAIT1();
        __syncthreads();

        const uint32_t sA = sbase + (uint32_t)(c & 1) * STAGE_B;
        #pragma unroll
        for (int ks = 0; ks < 4; ++ks) {
            const int colb = ks * 32 + lcol16;

            uint32_t bh[2][4];
            #pragma unroll
            for (int g = 0; g < 2; ++g) {
                uint32_t off = SWZ128((uint32_t)((wn + g * 16 + lrow) * 128 + colb));
                LDMATRIX_X4(bh[g][0], bh[g][1], bh[g][2], bh[g][3], sA + OFF_B + off);
            }

            #pragma unroll
            for (int mf = 0; mf < 5; ++mf) {
                uint32_t ah[4];
                uint32_t off = SWZ128((uint32_t)((wm + mf * 16 + lrow) * 128 + colb));
                LDMATRIX_X4(ah[0], ah[1], ah[2], ah[3], sA + OFF_A + off);
                #pragma unroll
                for (int g = 0; g < 2; ++g) {
                    MMA_FP16(acc[mf][g * 2 + 0], ah, bh[g][0], bh[g][2]);
                    MMA_FP16(acc[mf][g * 2 + 1], ah, bh[g][1], bh[g][3]);
                }
            }
        }
        __syncthreads();
    }

    #pragma unroll
    for (int mf = 0; mf < 5; ++mf) {
        #pragma unroll
        for (int nf = 0; nf < 4; ++nf) {
            const int r0 = m0 + wm + mf * 16 + (lane >> 2);
            const int cb = n0 + wn + nf * 8 + (lane & 3) * 2;
            const float b0 = __ldg(bias + cb);
            const float b1 = __ldg(bias + cb + 1);
            float2 v0;
            v0.x = fmaxf(acc[mf][nf][0] + b0, 0.0f);
            v0.y = fmaxf(acc[mf][nf][1] + b1, 0.0f);
            float2 v1;
            v1.x = fmaxf(acc[mf][nf][2] + b0, 0.0f);
            v1.y = fmaxf(acc[mf][nf][3] + b1, 0.0f);
            *(float2*)(g_h + (size_t)r0 * HID + cb) = v0;
            *(float2*)(g_h + (size_t)(r0 + 8) * HID + cb) = v1;
        }
    }
}

// ---------------------------------------------------------------------------
// fused layer-1: one CTA per batch row; rowptr + 4-way unrolled edge loop.
// ---------------------------------------------------------------------------
__global__ __launch_bounds__(256)
void out_kernel(const int* __restrict__ src,
                const float* __restrict__ b1, float* __restrict__ out) {
    __shared__ float sA[HID];
    __shared__ float sH[HID];
    __shared__ float logits[OUT_C];

    const int b = blockIdx.x;
    const int tid = threadIdx.x;
    const int start = g_rp1[b];
    const int end   = g_rp1[b + 1];

    float a0 = 0.0f, a1 = 0.0f, a2 = 0.0f, a3 = 0.0f;
    int e = start;
    for (; e + 3 < end; e += 4) {
        a0 += g_h[(size_t)src[e] * HID + tid];
        a1 += g_h[(size_t)src[e + 1] * HID + tid];
        a2 += g_h[(size_t)src[e + 2] * HID + tid];
        a3 += g_h[(size_t)src[e + 3] * HID + tid];
    }
    for (; e < end; ++e) {
        a0 += g_h[(size_t)src[e] * HID + tid];
    }
    sA[tid] = ((a0 + a1) + (a2 + a3)) / (float)max(end - start, 1);
    sH[tid] = g_h[(size_t)b * HID + tid];
    __syncthreads();

    const int w = tid >> 5;
    const int l = tid & 31;
    for (int c = w; c < OUT_C; c += 8) {
        const float* wl = g_w1t + (size_t)c * HID;
        const float* wr = g_w1t + (size_t)(OUT_C + c) * HID;
        float s = 0.0f;
        #pragma unroll
        for (int k = l; k < HID; k += 32) {
            s += sA[k] * wl[k] + sH[k] * wr[k];
        }
        #pragma unroll
        for (int o = 16; o; o >>= 1) {
            s += __shfl_xor_sync(0xffffffffu, s, o);
        }
        if (l == 0) logits[c] = s + b1[c];
    }
    __syncthreads();

    if (tid < 32) {
        float v0 = (tid < OUT_C) ? logits[tid] : -3.4e38f;
        float v1 = (tid + 32 < OUT_C) ? logits[tid + 32] : -3.4e38f;
        float m = fmaxf(v0, v1);
        #pragma unroll
        for (int o = 16; o; o >>= 1) {
            m = fmaxf(m, __shfl_xor_sync(0xffffffffu, m, o));
        }
        float es = ((tid < OUT_C) ? expf(v0 - m) : 0.0f) +
                   ((tid + 32 < OUT_C) ? expf(v1 - m) : 0.0f);
        #pragma unroll
        for (int o = 16; o; o >>= 1) {
            es += __shfl_xor_sync(0xffffffffu, es, o);
        }
        float lse = logf(es);
        if (tid < OUT_C) out[(size_t)b * OUT_C + tid] = v0 - m - lse;
        if (tid + 32 < OUT_C) out[(size_t)b * OUT_C + tid + 32] = v1 - m - lse;
    }
}

// ---------------------------------------------------------------------------
extern "C" void kernel_launch(void* const* d_in, const int* in_sizes, int n_in,
                              void* d_out, int out_size) {
    const float* x    = (const float*)d_in[0];
    const float* W_l0 = (const float*)d_in[1];
    const float* b_l0 = (const float*)d_in[2];
    const float* W_r0 = (const float*)d_in[3];
    const float* W_l1 = (const float*)d_in[4];
    const float* b_l1 = (const float*)d_in[5];
    const float* W_r1 = (const float*)d_in[6];
    const int* src0   = (const int*)d_in[7];
    const int* dst0   = (const int*)d_in[8];
    const int* src1   = (const int*)d_in[9];
    const int* dst1   = (const int*)d_in[10];
    float* out = (float*)d_out;

    static int s_attr_done = 0;
    if (!s_attr_done) {
        cudaFuncSetAttribute(gemm0_mma, cudaFuncAttributeMaxDynamicSharedMemorySize,
                             GSM_TOTAL);
        s_attr_done = 1;
    }

    rowptr_kernel<<<(N1_ + 1 + 255) / 256, 256>>>(dst0, dst1);
    agg0x_kernel<<<N1_ + PREP_BLOCKS, 256>>>(x, src0, W_l0, W_r0, W_l1, W_r1);
    gemm0_mma<<<128, 256, GSM_TOTAL>>>(b_l0);
    out_kernel<<<B_, 256>>>(src1, b_l1, out);
}

// round 13
// speedup vs baseline: 1.4785x; 1.0026x over previous
#include <cuda_runtime.h>
#include <cuda_fp16.h>
#include <cstdint>

#define N0_   260000
#define N1_   10240
#define B_    1024
#define E0_   256000
#define E1_   10240
#define IN_C  602
#define HID   256
#define OUT_C 41
#define KHALF 640
#define KTOT  1280
#define NCHUNK 20

// ---------------- scratch ----------------------------------------------------
__device__ __half g_a[(size_t)N1_ * KTOT];    // A (fp16) [10240][1280]
__device__ __half g_wt[(size_t)HID * KTOT];   // W^T (fp16) [256][1280]
__device__ float g_h[(size_t)N1_ * HID];
__device__ float g_w1t[2 * OUT_C * HID];      // [c][k] transposed layer-1 weights
__device__ int   g_rp0[N1_ + 1];              // CSR row ptr, layer 0
__device__ int   g_rp1[B_ + 1];               // CSR row ptr, layer 1

// ---------------- portable PTX macros ---------------------------------------
#define CP_ASYNC16(dst, src) \
    asm volatile("cp.async.cg.shared.global [%0], [%1], 16;" \
        :: "r"((uint32_t)(dst)), "l"(src) : "memory")
#define CP_COMMIT() asm volatile("cp.async.commit_group;" ::: "memory")
#define CP_WAIT1()  asm volatile("cp.async.wait_group 1;" ::: "memory")

#define LDMATRIX_X4(r0, r1, r2, r3, addr) \
    asm volatile("ldmatrix.sync.aligned.m8n8.x4.shared.b16 {%0,%1,%2,%3}, [%4];" \
        : "=r"(r0), "=r"(r1), "=r"(r2), "=r"(r3) : "r"((uint32_t)(addr)))

#define MMA_FP16(d, a, b0_, b1_) \
    asm volatile("mma.sync.aligned.m16n8k16.row.col.f32.f16.f16.f32 " \
        "{%0,%1,%2,%3}, {%4,%5,%6,%7}, {%8,%9}, {%0,%1,%2,%3};" \
        : "+f"((d)[0]), "+f"((d)[1]), "+f"((d)[2]), "+f"((d)[3]) \
        : "r"((a)[0]), "r"((a)[1]), "r"((a)[2]), "r"((a)[3]), \
          "r"(b0_), "r"(b1_))

#define SWZ128(o) ((o) ^ (((o) >> 3) & 0x70))

// ---------------------------------------------------------------------------
__device__ __forceinline__ int lower_bound_i(const int* __restrict__ a, int n, int v) {
    int lo = 0;
    int hi = n;
    while (lo < hi) {
        int mid = (lo + hi) >> 1;
        if (a[mid] < v) lo = mid + 1; else hi = mid;
    }
    return lo;
}

// ---------------------------------------------------------------------------
// rowptr: parallel binary searches (one thread per target), both layers.
// ---------------------------------------------------------------------------
__global__ void rowptr_kernel(const int* __restrict__ dst0,
                              const int* __restrict__ dst1) {
    int i = blockIdx.x * blockDim.x + threadIdx.x;
    if (i <= N1_) g_rp0[i] = lower_bound_i(dst0, E0_, i);
    if (i <= B_)  g_rp1[i] = lower_bound_i(dst1, E1_, i);
}

// ---------------------------------------------------------------------------
// fused: layer-0 segment mean (+x-row copy) AND weight prep, one launch.
// ---------------------------------------------------------------------------
#define W0_ELEMS (2 * HID * KHALF)
#define W1_ELEMS (2 * OUT_C * HID)
#define PREP_BLOCKS ((W0_ELEMS + W1_ELEMS + 255) / 256)

__global__ __launch_bounds__(256)
void agg0x_kernel(const float* __restrict__ x,
                  const int* __restrict__ src,
                  const float* __restrict__ Wl0,
                  const float* __restrict__ Wr0,
                  const float* __restrict__ Wl1,
                  const float* __restrict__ Wr1) {
    __shared__ float sred[8][640];

    const int t = blockIdx.x;
    const int tid = threadIdx.x;

    if (t >= N1_) {
        int i = (t - N1_) * 256 + tid;
        if (i < W0_ELEMS) {
            int m = i / (HID * KHALF);
            int rem = i % (HID * KHALF);
            int n = rem / KHALF;
            int k = rem % KHALF;
            const float* W = m ? Wr0 : Wl0;
            float v = (k < IN_C) ? W[(size_t)k * HID + n] : 0.0f;
            g_wt[(size_t)n * KTOT + (size_t)m * KHALF + k] = __float2half_rn(v);
        } else {
            int j = i - W0_ELEMS;
            if (j < W1_ELEMS) {
                int m = j / (OUT_C * HID);
                int rem = j % (OUT_C * HID);
                int c = rem / HID;
                int k = rem % HID;
                const float* W = m ? Wr1 : Wl1;
                g_w1t[j] = W[(size_t)k * OUT_C + c];
            }
        }
        return;
    }

    const int start = g_rp0[t];
    const int end   = g_rp0[t + 1];
    const int w = tid >> 5;
    const int l = tid & 31;

    float2 acc[10];
    #pragma unroll
    for (int i = 0; i < 10; ++i) acc[i] = make_float2(0.f, 0.f);

    int e = start + w;
    // unroll-2 over warp-strided edges: 20 outstanding loads per lane
    for (; e + 8 < end; e += 16) {
        const float* p  = x + (size_t)src[e] * IN_C;
        const float* p2 = x + (size_t)src[e + 8] * IN_C;
        #pragma unroll
        for (int i = 0; i < 10; ++i) {
            const int col = 2 * (l + 32 * i);
            if (col + 1 < IN_C) {
                float2 v  = *(const float2*)(p + col);
                float2 v2 = *(const float2*)(p2 + col);
                acc[i].x += v.x + v2.x;
                acc[i].y += v.y + v2.y;
            }
        }
    }
    if (e < end) {
        const float* p = x + (size_t)src[e] * IN_C;
        #pragma unroll
        for (int i = 0; i < 10; ++i) {
            const int col = 2 * (l + 32 * i);
            if (col + 1 < IN_C) {
                float2 v = *(const float2*)(p + col);
                acc[i].x += v.x;
                acc[i].y += v.y;
            }
        }
    }

    #pragma unroll
    for (int i = 0; i < 10; ++i) {
        const int col = 2 * (l + 32 * i);
        *(float2*)&sred[w][col] = acc[i];
    }
    __syncthreads();

    const float inv = 1.0f / (float)max(end - start, 1);
    __half* A = g_a + (size_t)t * KTOT;

    {
        const int col = tid;
        float s = sred[0][col] + sred[1][col] + sred[2][col] + sred[3][col]
                + sred[4][col] + sred[5][col] + sred[6][col] + sred[7][col];
        A[col] = __float2half_rn(s * inv);
    }
    {
        const int col = tid + 256;
        float s = sred[0][col] + sred[1][col] + sred[2][col] + sred[3][col]
                + sred[4][col] + sred[5][col] + sred[6][col] + sred[7][col];
        A[col] = __float2half_rn(s * inv);
    }
    if (tid < 128) {
        const int col = tid + 512;
        float s = sred[0][col] + sred[1][col] + sred[2][col] + sred[3][col]
                + sred[4][col] + sred[5][col] + sred[6][col] + sred[7][col];
        A[col] = __float2half_rn(s * inv);
    }

    // x row t -> cols 640..1279 (fp16, padded)
    const int c0 = 2 * tid;
    const int c1 = 512 + 2 * tid;
    const bool has2 = (tid < 45);
    const float* xr = x + (size_t)t * IN_C;
    float2 v0 = *(const float2*)(xr + c0);
    A[KHALF + c0] = __float2half_rn(v0.x);
    A[KHALF + c0 + 1] = __float2half_rn(v0.y);
    if (has2) {
        float2 v1 = *(const float2*)(xr + c1);
        A[KHALF + c1] = __float2half_rn(v1.x);
        A[KHALF + c1 + 1] = __float2half_rn(v1.y);
    } else if (tid < 64) {
        A[KHALF + c1] = __float2half_rn(0.0f);
        A[KHALF + c1 + 1] = __float2half_rn(0.0f);
    }
}

// ---------------------------------------------------------------------------
// layer-0 GEMM (proven): fp16 mma.m16n8k16, tile 160x128, grid 128 = 1 wave.
// ---------------------------------------------------------------------------
#define TM        160
#define OFF_A     0u
#define OFF_B     20480u
#define STAGE_B   36864u
#define GSM_TOTAL (2 * 36864)

__device__ __forceinline__ void load_stage(uint32_t sb, int kc, int m0, int n0, int tid) {
    #pragma unroll
    for (int j = 0; j < 5; ++j) {
        int i = tid + 256 * j;
        int row = i >> 3;
        int q = i & 7;
        uint32_t d = sb + OFF_A + SWZ128((uint32_t)(row * 128 + q * 16));
        CP_ASYNC16(d, g_a + (size_t)(m0 + row) * KTOT + kc + q * 8);
    }
    #pragma unroll
    for (int j = 0; j < 4; ++j) {
        int i = tid + 256 * j;
        int row = i >> 3;
        int q = i & 7;
        uint32_t d = sb + OFF_B + SWZ128((uint32_t)(row * 128 + q * 16));
        CP_ASYNC16(d, g_wt + (size_t)(n0 + row) * KTOT + kc + q * 8);
    }
}

__global__ __launch_bounds__(256, 1)
void gemm0_mma(const float* __restrict__ bias) {
    extern __shared__ char smem_raw[];
    const uint32_t sbase = (uint32_t)__cvta_generic_to_shared(smem_raw);

    const int tid = threadIdx.x;
    const int wid = tid >> 5;
    const int lane = tid & 31;
    const int m0 = (blockIdx.x >> 1) * TM;
    const int n0 = (blockIdx.x & 1) * 128;
    const int wm = (wid & 1) * 80;
    const int wn = (wid >> 1) * 32;

    float acc[5][4][4];
    #pragma unroll
    for (int a = 0; a < 5; ++a)
        #pragma unroll
        for (int b = 0; b < 4; ++b)
            #pragma unroll
            for (int c = 0; c < 4; ++c) acc[a][b][c] = 0.0f;

    const int lrow = lane & 15;
    const int lcol16 = (lane >> 4) * 16;

    load_stage(sbase, 0, m0, n0, tid);
    CP_COMMIT();

    for (int c = 0; c < NCHUNK; ++c) {
        if (c + 1 < NCHUNK) {
            load_stage(sbase + (uint32_t)((c + 1) & 1) * STAGE_B, (c + 1) * 64, m0, n0, tid);
        }
        CP_COMMIT();
        CP_WAIT1();
        __syncthreads();

        const uint32_t sA = sbase + (uint32_t)(c & 1) * STAGE_B;
        #pragma unroll
        for (int ks = 0; ks < 4; ++ks) {
            const int colb = ks * 32 + lcol16;

            uint32_t bh[2][4];
            #pragma unroll
            for (int g = 0; g < 2; ++g) {
                uint32_t off = SWZ128((uint32_t)((wn + g * 16 + lrow) * 128 + colb));
                LDMATRIX_X4(bh[g][0], bh[g][1], bh[g][2], bh[g][3], sA + OFF_B + off);
            }

            #pragma unroll
            for (int mf = 0; mf < 5; ++mf) {
                uint32_t ah[4];
                uint32_t off = SWZ128((uint32_t)((wm + mf * 16 + lrow) * 128 + colb));
                LDMATRIX_X4(ah[0], ah[1], ah[2], ah[3], sA + OFF_A + off);
                #pragma unroll
                for (int g = 0; g < 2; ++g) {
                    MMA_FP16(acc[mf][g * 2 + 0], ah, bh[g][0], bh[g][2]);
                    MMA_FP16(acc[mf][g * 2 + 1], ah, bh[g][1], bh[g][3]);
                }
            }
        }
        __syncthreads();
    }

    #pragma unroll
    for (int mf = 0; mf < 5; ++mf) {
        #pragma unroll
        for (int nf = 0; nf < 4; ++nf) {
            const int r0 = m0 + wm + mf * 16 + (lane >> 2);
            const int cb = n0 + wn + nf * 8 + (lane & 3) * 2;
            const float b0 = __ldg(bias + cb);
            const float b1 = __ldg(bias + cb + 1);
            float2 v0;
            v0.x = fmaxf(acc[mf][nf][0] + b0, 0.0f);
            v0.y = fmaxf(acc[mf][nf][1] + b1, 0.0f);
            float2 v1;
            v1.x = fmaxf(acc[mf][nf][2] + b0, 0.0f);
            v1.y = fmaxf(acc[mf][nf][3] + b1, 0.0f);
            *(float2*)(g_h + (size_t)r0 * HID + cb) = v0;
            *(float2*)(g_h + (size_t)(r0 + 8) * HID + cb) = v1;
        }
    }
}

// ---------------------------------------------------------------------------
// fused layer-1: TWO rows per CTA (grid 512) — weight loads shared between
// rows in the logit loop; both gathers interleave for 2x MLP.
// ---------------------------------------------------------------------------
__global__ __launch_bounds__(256)
void out_kernel(const int* __restrict__ src,
                const float* __restrict__ b1, float* __restrict__ out) {
    __shared__ float sA[2][HID];
    __shared__ float sH[2][HID];
    __shared__ float logits[2][OUT_C];

    const int b0 = blockIdx.x * 2;
    const int tid = threadIdx.x;

    #pragma unroll
    for (int r = 0; r < 2; ++r) {
        const int b = b0 + r;
        const int start = g_rp1[b];
        const int end   = g_rp1[b + 1];
        float a0 = 0.0f, a1 = 0.0f, a2 = 0.0f, a3 = 0.0f;
        int e = start;
        for (; e + 3 < end; e += 4) {
            a0 += g_h[(size_t)src[e] * HID + tid];
            a1 += g_h[(size_t)src[e + 1] * HID + tid];
            a2 += g_h[(size_t)src[e + 2] * HID + tid];
            a3 += g_h[(size_t)src[e + 3] * HID + tid];
        }
        for (; e < end; ++e) {
            a0 += g_h[(size_t)src[e] * HID + tid];
        }
        sA[r][tid] = ((a0 + a1) + (a2 + a3)) / (float)max(end - start, 1);
        sH[r][tid] = g_h[(size_t)b * HID + tid];
    }
    __syncthreads();

    const int w = tid >> 5;
    const int l = tid & 31;
    for (int c = w; c < OUT_C; c += 8) {
        const float* wl = g_w1t + (size_t)c * HID;
        const float* wr = g_w1t + (size_t)(OUT_C + c) * HID;
        float s0 = 0.0f;
        float s1 = 0.0f;
        #pragma unroll
        for (int k = l; k < HID; k += 32) {
            const float wlv = wl[k];
            const float wrv = wr[k];
            s0 += sA[0][k] * wlv + sH[0][k] * wrv;
            s1 += sA[1][k] * wlv + sH[1][k] * wrv;
        }
        #pragma unroll
        for (int o = 16; o; o >>= 1) {
            s0 += __shfl_xor_sync(0xffffffffu, s0, o);
            s1 += __shfl_xor_sync(0xffffffffu, s1, o);
        }
        if (l == 0) {
            logits[0][c] = s0 + b1[c];
            logits[1][c] = s1 + b1[c];
        }
    }
    __syncthreads();

    if (tid < 64) {
        const int r = tid >> 5;
        const int ll = tid & 31;
        float v0 = (ll < OUT_C) ? logits[r][ll] : -3.4e38f;
        float v1 = (ll + 32 < OUT_C) ? logits[r][ll + 32] : -3.4e38f;
        float m = fmaxf(v0, v1);
        #pragma unroll
        for (int o = 16; o; o >>= 1) {
            m = fmaxf(m, __shfl_xor_sync(0xffffffffu, m, o));
        }
        float es = ((ll < OUT_C) ? expf(v0 - m) : 0.0f) +
                   ((ll + 32 < OUT_C) ? expf(v1 - m) : 0.0f);
        #pragma unroll
        for (int o = 16; o; o >>= 1) {
            es += __shfl_xor_sync(0xffffffffu, es, o);
        }
        float lse = logf(es);
        const int b = b0 + r;
        if (ll < OUT_C) out[(size_t)b * OUT_C + ll] = v0 - m - lse;
        if (ll + 32 < OUT_C) out[(size_t)b * OUT_C + ll + 32] = v1 - m - lse;
    }
}

// ---------------------------------------------------------------------------
extern "C" void kernel_launch(void* const* d_in, const int* in_sizes, int n_in,
                              void* d_out, int out_size) {
    const float* x    = (const float*)d_in[0];
    const float* W_l0 = (const float*)d_in[1];
    const float* b_l0 = (const float*)d_in[2];
    const float* W_r0 = (const float*)d_in[3];
    const float* W_l1 = (const float*)d_in[4];
    const float* b_l1 = (const float*)d_in[5];
    const float* W_r1 = (const float*)d_in[6];
    const int* src0   = (const int*)d_in[7];
    const int* dst0   = (const int*)d_in[8];
    const int* src1   = (const int*)d_in[9];
    const int* dst1   = (const int*)d_in[10];
    float* out = (float*)d_out;

    static int s_attr_done = 0;
    if (!s_attr_done) {
        cudaFuncSetAttribute(gemm0_mma, cudaFuncAttributeMaxDynamicSharedMemorySize,
                             GSM_TOTAL);
        s_attr_done = 1;
    }

    rowptr_kernel<<<(N1_ + 1 + 255) / 256, 256>>>(dst0, dst1);
    agg0x_kernel<<<N1_ + PREP_BLOCKS, 256>>>(x, src0, W_l0, W_r0, W_l1, W_r1);
    gemm0_mma<<<128, 256, GSM_TOTAL>>>(b_l0);
    out_kernel<<<B_ / 2, 256>>>(src1, b_l1, out);
}